// round 16
// baseline (speedup 1.0000x reference)
#include <cuda_runtime.h>
#include <cuda_bf16.h>

#define N_NODES 50000
#define N_EDGES 800000
#define IN_FEAT 256
#define DIM_H 64
#define DIM_OUT 64
#define N_B 72                                   // 64 h cols + a_dst col + 7 pad
#define SLOT 64                                  // max degree capacity (P(overflow)~1e-14)

// scratch (static device globals; no allocations allowed)
__device__ float g_h_src[N_NODES * DIM_H];   // 12.8 MB
__device__ float g_a_src[N_NODES];
__device__ float g_a_dst[N_NODES];
__device__ float g_agg[N_NODES * DIM_H];     // 12.8 MB
__device__ unsigned g_Wp_hi[N_B * 128];      // B' packed bf16x2, [n][k/2]
__device__ unsigned g_Wp_lo[N_B * 128];
__device__ int   g_cnt[N_NODES];
__device__ int   g_slot[N_NODES * SLOT];     // src ids bucketed by dst (12.8 MB)

// edge_index delivered as int32 (evidence: R1 int64 interpretation -> illegal access)
__device__ __forceinline__ int load_src(const int* e32, int i) { return e32[i]; }
__device__ __forceinline__ int load_dst(const int* e32, int i) { return e32[N_EDGES + i]; }

// split fp32 pair into bf16-hi and bf16-lo packed u32 (low 16 bits = first elem)
__device__ __forceinline__ void cvt2(float a, float b, unsigned& hi, unsigned& lo) {
    __nv_bfloat16 ha = __float2bfloat16(a), hb = __float2bfloat16(b);
    float la = a - __bfloat162float(ha);
    float lb = b - __bfloat162float(hb);
    __nv_bfloat16 hla = __float2bfloat16(la), hlb = __float2bfloat16(lb);
    hi = ((unsigned)__bfloat16_as_ushort(hb) << 16) | (unsigned)__bfloat16_as_ushort(ha);
    lo = ((unsigned)__bfloat16_as_ushort(hlb) << 16) | (unsigned)__bfloat16_as_ushort(hla);
}

__device__ __forceinline__ void mma_bf16(float& c0, float& c1, float& c2, float& c3,
                                         unsigned a0, unsigned a1, unsigned a2, unsigned a3,
                                         unsigned b0, unsigned b1) {
    asm volatile(
        "mma.sync.aligned.m16n8k16.row.col.f32.bf16.bf16.f32 "
        "{%0,%1,%2,%3}, {%4,%5,%6,%7}, {%8,%9}, {%0,%1,%2,%3};"
        : "+f"(c0), "+f"(c1), "+f"(c2), "+f"(c3)
        : "r"(a0), "r"(a1), "r"(a2), "r"(a3), "r"(b0), "r"(b1));
}

// ---------------------------------------------------------------------------
// pack B' = [W_src | W_dst@att_dst | zeros] into bf16 hi/lo, [n][k/2]
__global__ void pack_kernel(const float* __restrict__ Wsrc,
                            const float* __restrict__ Wdst,
                            const float* __restrict__ attd) {
    int idx = blockIdx.x * blockDim.x + threadIdx.x;   // 9216 tasks
    if (idx < 8192) {
        int n = idx & 63, kp = idx >> 6;               // coalesced over n
        float w0 = Wsrc[(2 * kp) * 64 + n];
        float w1 = Wsrc[(2 * kp + 1) * 64 + n];
        unsigned hi, lo;
        cvt2(w0, w1, hi, lo);
        g_Wp_hi[n * 128 + kp] = hi;
        g_Wp_lo[n * 128 + kp] = lo;
    } else if (idx < 8192 + 1024) {
        int idx2 = idx - 8192;
        int kp = idx2 & 127, n = 64 + (idx2 >> 7);
        if (n == 64) {
            float w0 = 0.f, w1 = 0.f;
#pragma unroll
            for (int j = 0; j < DIM_H; j++) {
                float aj = attd[j];
                w0 += Wdst[(2 * kp) * 64 + j] * aj;
                w1 += Wdst[(2 * kp + 1) * 64 + j] * aj;
            }
            unsigned hi, lo;
            cvt2(w0, w1, hi, lo);
            g_Wp_hi[n * 128 + kp] = hi;
            g_Wp_lo[n * 128 + kp] = lo;
        } else {
            g_Wp_hi[n * 128 + kp] = 0u;
            g_Wp_lo[n * 128 + kp] = 0u;
        }
    }
}

// ---------------------------------------------------------------------------
// [h_src | a_dst] = x @ B' via split-bf16 MMA; a_src = h_src @ att_src (epilogue)
__global__ __launch_bounds__(128, 4) void proj_mma_kernel(const float* __restrict__ x,
                                                          const float* __restrict__ atts) {
    __shared__ unsigned Xhi[64][20], Xlo[64][20];   // [node][k/2], stride 20 u32
    __shared__ unsigned Whi[N_B][20], Wlo[N_B][20]; // [n][k/2]
    __shared__ float att_s[64];

    int tx = threadIdx.x;
    int w = tx >> 5, lane = tx & 31;
    int g = lane >> 2, t = lane & 3;
    int node0 = blockIdx.x * 64;
    int m0 = w * 16;

    if (tx < 64) att_s[tx] = atts[tx];

    float c[9][4];
#pragma unroll
    for (int i = 0; i < 9; i++)
#pragma unroll
        for (int j = 0; j < 4; j++) c[i][j] = 0.f;

    for (int kc = 0; kc < IN_FEAT / 32; kc++) {
        __syncthreads();
#pragma unroll
        for (int i = tx; i < 512; i += 128) {
            int nd = i >> 3, kq = i & 7;
            int row = node0 + nd; if (row >= N_NODES) row = N_NODES - 1;
            float4 v = ((const float4*)(x + (size_t)row * IN_FEAT + kc * 32))[kq];
            unsigned hi0, lo0, hi1, lo1;
            cvt2(v.x, v.y, hi0, lo0);
            cvt2(v.z, v.w, hi1, lo1);
            Xhi[nd][kq * 2 + 0] = hi0; Xlo[nd][kq * 2 + 0] = lo0;
            Xhi[nd][kq * 2 + 1] = hi1; Xlo[nd][kq * 2 + 1] = lo1;
        }
#pragma unroll
        for (int i = tx; i < N_B * 16; i += 128) {
            int n = i >> 4, j = i & 15;
            Whi[n][j] = g_Wp_hi[n * 128 + kc * 16 + j];
            Wlo[n][j] = g_Wp_lo[n * 128 + kc * 16 + j];
        }
        __syncthreads();

#pragma unroll
        for (int ks = 0; ks < 2; ks++) {
            int kb = ks * 8;
            unsigned a0h = Xhi[m0 + g][t + kb],     a1h = Xhi[m0 + g + 8][t + kb];
            unsigned a2h = Xhi[m0 + g][t + 4 + kb], a3h = Xhi[m0 + g + 8][t + 4 + kb];
            unsigned a0l = Xlo[m0 + g][t + kb],     a1l = Xlo[m0 + g + 8][t + kb];
            unsigned a2l = Xlo[m0 + g][t + 4 + kb], a3l = Xlo[m0 + g + 8][t + 4 + kb];
#pragma unroll
            for (int nt = 0; nt < 9; nt++) {
                unsigned b0h = Whi[nt * 8 + g][t + kb], b1h = Whi[nt * 8 + g][t + 4 + kb];
                unsigned b0l = Wlo[nt * 8 + g][t + kb], b1l = Wlo[nt * 8 + g][t + 4 + kb];
                mma_bf16(c[nt][0], c[nt][1], c[nt][2], c[nt][3],
                         a0h, a1h, a2h, a3h, b0h, b1h);
                mma_bf16(c[nt][0], c[nt][1], c[nt][2], c[nt][3],
                         a0h, a1h, a2h, a3h, b0l, b1l);
                mma_bf16(c[nt][0], c[nt][1], c[nt][2], c[nt][3],
                         a0l, a1l, a2l, a3l, b0h, b1h);
            }
        }
    }

    int n_lo = node0 + m0 + g;
    int n_hi = n_lo + 8;
#pragma unroll
    for (int nt = 0; nt < 8; nt++) {
        int f = nt * 8 + t * 2;
        if (n_lo < N_NODES) {
            float2 v = {c[nt][0], c[nt][1]};
            *(float2*)(g_h_src + (size_t)n_lo * DIM_H + f) = v;
        }
        if (n_hi < N_NODES) {
            float2 v = {c[nt][2], c[nt][3]};
            *(float2*)(g_h_src + (size_t)n_hi * DIM_H + f) = v;
        }
    }
    float p_lo = 0.f, p_hi = 0.f;
#pragma unroll
    for (int nt = 0; nt < 8; nt++) {
        int f = nt * 8 + t * 2;
        p_lo += c[nt][0] * att_s[f] + c[nt][1] * att_s[f + 1];
        p_hi += c[nt][2] * att_s[f] + c[nt][3] * att_s[f + 1];
    }
#pragma unroll
    for (int o = 1; o < 4; o <<= 1) {
        p_lo += __shfl_xor_sync(0xFFFFFFFFu, p_lo, o);
        p_hi += __shfl_xor_sync(0xFFFFFFFFu, p_hi, o);
    }
    if (t == 0) {
        if (n_lo < N_NODES) { g_a_src[n_lo] = p_lo; g_a_dst[n_lo] = c[8][0]; }
        if (n_hi < N_NODES) { g_a_src[n_hi] = p_hi; g_a_dst[n_hi] = c[8][2]; }
    }
}

// ---------------------------------------------------------------------------
// one-pass counting sort into fixed 64-entry slots
__global__ void histbin_kernel(const int* __restrict__ e32) {
    int i = blockIdx.x * blockDim.x + threadIdx.x;
    if (i >= N_EDGES) return;
    int s = load_src(e32, i);
    int d = load_dst(e32, i);
    int pos = atomicAdd(&g_cnt[d], 1);
    if (pos < SLOT) g_slot[d * SLOT + pos] = s;   // overflow prob ~1e-14: drop-safe
}

// ---------------------------------------------------------------------------
// gather: per-dst segment softmax + weighted sum.
// Half-warp per edge: half = lane>>4 owns edge, (lane&15)*4 = feat offset,
// one LDG.128 per lane per edge-pair. 4 edges per iteration (MLP 2).
// ex_l is zero for lanes >= n, so over-indexed shfl slots contribute 0.
__global__ __launch_bounds__(256) void gather_kernel() {
    int node = (blockIdx.x * blockDim.x + threadIdx.x) >> 5;
    int lane = threadIdx.x & 31;
    if (node >= N_NODES) return;
    int cnt = min(g_cnt[node], SLOT);
    float ad = g_a_dst[node];
    const int* sl = g_slot + node * SLOT;
    int half = lane >> 4;
    int fq = (lane & 15) * 4;

    float ax = 0.f, ay = 0.f, az = 0.f, aw = 0.f, denom = 0.f;
    for (int base = 0; base < cnt; base += 32) {
        int n = min(32, cnt - base);
        int s_l = 0; float ex_l = 0.f;
        if (lane < n) {
            s_l = sl[base + lane];
            float e = g_a_src[s_l] + ad;
            e = e > 0.f ? e : 0.2f * e;
            ex_l = __expf(e);
        }
        for (int j = 0; j < n; j += 4) {
            // half 0 handles edges j, j+2; half 1 handles j+1, j+3
            float exA = __shfl_sync(0xFFFFFFFFu, ex_l, j + half);
            int   sA  = __shfl_sync(0xFFFFFFFFu, s_l,  j + half);
            float exB = __shfl_sync(0xFFFFFFFFu, ex_l, j + 2 + half);
            int   sB  = __shfl_sync(0xFFFFFFFFu, s_l,  j + 2 + half);
            float4 vA = *(const float4*)(g_h_src + (size_t)sA * DIM_H + fq);
            float4 vB = *(const float4*)(g_h_src + (size_t)sB * DIM_H + fq);
            denom += exA + exB;
            ax += exA * vA.x + exB * vB.x;
            ay += exA * vA.y + exB * vB.y;
            az += exA * vA.z + exB * vB.z;
            aw += exA * vA.w + exB * vB.w;
        }
    }
    // merge the two half-warp partials (each half saw a disjoint edge subset)
    ax += __shfl_xor_sync(0xFFFFFFFFu, ax, 16);
    ay += __shfl_xor_sync(0xFFFFFFFFu, ay, 16);
    az += __shfl_xor_sync(0xFFFFFFFFu, az, 16);
    aw += __shfl_xor_sync(0xFFFFFFFFu, aw, 16);
    denom += __shfl_xor_sync(0xFFFFFFFFu, denom, 16);

    if (half == 0) {
        float inv = (cnt > 0) ? (1.f / denom) : 0.f;
        float4 r = {ax * inv, ay * inv, az * inv, aw * inv};
        *(float4*)(g_agg + (size_t)node * DIM_H + fq) = r;
    }
}

// ---------------------------------------------------------------------------
// out = relu(agg + bias_conv) @ W_lin + b_lin
__global__ __launch_bounds__(128, 4) void out_kernel(const float* __restrict__ Wlin,
                                                     const float* __restrict__ bias_conv,
                                                     const float* __restrict__ blin,
                                                     float* __restrict__ out) {
    __shared__ float Hs[32][129];
    __shared__ __align__(16) float Ws_s[32][64];
    __shared__ float bc_s[32], bl_s[64];

    int tx = threadIdx.x;
    int node0 = blockIdx.x * 128;
    int fg = (tx >> 2) & 7;
    int ng = (tx & 3) + ((tx >> 5) << 2);

    if (tx < 64) bl_s[tx] = blin[tx];

    float acc[8][8];
#pragma unroll
    for (int i = 0; i < 8; i++)
#pragma unroll
        for (int j = 0; j < 8; j++) acc[i][j] = 0.f;

    for (int kc = 0; kc < DIM_H / 32; kc++) {
        __syncthreads();
        if (tx < 32) bc_s[tx] = bias_conv[kc * 32 + tx];
        __syncthreads();
#pragma unroll
        for (int i = tx; i < 1024; i += 128) {
            int nd = i >> 3, kq = i & 7;
            int row = node0 + nd; if (row >= N_NODES) row = N_NODES - 1;
            float4 v = ((const float4*)(g_agg + (size_t)row * DIM_H + kc * 32))[kq];
            float h0 = v.x + bc_s[kq * 4 + 0];
            float h1 = v.y + bc_s[kq * 4 + 1];
            float h2 = v.z + bc_s[kq * 4 + 2];
            float h3 = v.w + bc_s[kq * 4 + 3];
            Hs[kq * 4 + 0][nd] = h0 > 0.f ? h0 : 0.f;
            Hs[kq * 4 + 1][nd] = h1 > 0.f ? h1 : 0.f;
            Hs[kq * 4 + 2][nd] = h2 > 0.f ? h2 : 0.f;
            Hs[kq * 4 + 3][nd] = h3 > 0.f ? h3 : 0.f;
        }
        const float4* w4 = (const float4*)(Wlin + kc * 32 * 64);
        float4* ws4 = (float4*)&Ws_s[0][0];
#pragma unroll
        for (int i = tx; i < 512; i += 128) ws4[i] = w4[i];
        __syncthreads();

#pragma unroll
        for (int k = 0; k < 32; k++) {
            float hv[8];
#pragma unroll
            for (int i = 0; i < 8; i++) hv[i] = Hs[k][ng * 8 + i];
            float4 w0 = ((const float4*)&Ws_s[k][0])[fg * 2 + 0];
            float4 w1 = ((const float4*)&Ws_s[k][0])[fg * 2 + 1];
            float wv[8] = {w0.x, w0.y, w0.z, w0.w, w1.x, w1.y, w1.z, w1.w};
#pragma unroll
            for (int i = 0; i < 8; i++)
#pragma unroll
                for (int j = 0; j < 8; j++) acc[i][j] += hv[i] * wv[j];
        }
    }

    int nmax = N_NODES - node0;
#pragma unroll
    for (int i = 0; i < 8; i++) {
        int nd = ng * 8 + i;
        if (nd < nmax) {
            float4* o = (float4*)(out + (size_t)(node0 + nd) * DIM_OUT + fg * 8);
            float4 v0 = {acc[i][0] + bl_s[fg * 8 + 0], acc[i][1] + bl_s[fg * 8 + 1],
                         acc[i][2] + bl_s[fg * 8 + 2], acc[i][3] + bl_s[fg * 8 + 3]};
            float4 v1 = {acc[i][4] + bl_s[fg * 8 + 4], acc[i][5] + bl_s[fg * 8 + 5],
                         acc[i][6] + bl_s[fg * 8 + 6], acc[i][7] + bl_s[fg * 8 + 7]};
            o[0] = v0; o[1] = v1;
        }
    }
}

// ---------------------------------------------------------------------------
extern "C" void kernel_launch(void* const* d_in, const int* in_sizes, int n_in,
                              void* d_out, int out_size) {
    const float* x     = (const float*)d_in[0];
    const int*   e32   = (const int*)d_in[1];
    const float* Wsrc  = (const float*)d_in[2];
    const float* Wdst  = (const float*)d_in[3];
    const float* atts  = (const float*)d_in[4];
    const float* attd  = (const float*)d_in[5];
    const float* bconv = (const float*)d_in[6];
    const float* Wlin  = (const float*)d_in[7];
    const float* blin  = (const float*)d_in[8];
    float*       out   = (float*)d_out;

    static cudaStream_t sB = nullptr;
    static cudaEvent_t evFork = nullptr, evB = nullptr;
    if (!sB) {
        cudaStreamCreateWithFlags(&sB, cudaStreamNonBlocking);
        cudaEventCreateWithFlags(&evFork, cudaEventDisableTiming);
        cudaEventCreateWithFlags(&evB, cudaEventDisableTiming);
    }

    void* cnt_ptr = nullptr;
    cudaGetSymbolAddress(&cnt_ptr, g_cnt);

    const int PROJ_BLOCKS = (N_NODES + 63) / 64;     // 782
    const int NODE_BLOCKS = (N_NODES + 127) / 128;   // 391
    const int EDGE_BLOCKS = (N_EDGES + 255) / 256;   // 3125

    // fork stream B off the origin stream
    cudaEventRecord(evFork, 0);
    cudaStreamWaitEvent(sB, evFork, 0);

    // stream B: one-pass edge bucketing (independent of A-chain)
    cudaMemsetAsync(cnt_ptr, 0, (size_t)N_NODES * sizeof(int), sB);
    histbin_kernel<<<EDGE_BLOCKS, 256, 0, sB>>>(e32);
    cudaEventRecord(evB, sB);

    // origin stream: pack B' then fused projection (h_src + a_src + a_dst)
    pack_kernel<<<36, 256>>>(Wsrc, Wdst, attd);
    proj_mma_kernel<<<PROJ_BLOCKS, 128>>>(x, atts);

    // join, then tail
    cudaStreamWaitEvent(0, evB, 0);
    gather_kernel<<<(N_NODES * 32 + 255) / 256, 256>>>();
    out_kernel<<<NODE_BLOCKS, 128>>>(Wlin, bconv, blin, out);
}

// round 17
// speedup vs baseline: 1.0437x; 1.0437x over previous
#include <cuda_runtime.h>
#include <cuda_bf16.h>

#define N_NODES 50000
#define N_EDGES 800000
#define IN_FEAT 256
#define DIM_H 64
#define DIM_OUT 64
#define N_B 72                                   // 64 h cols + a_dst col + 7 pad
#define SLOT 64                                  // max degree capacity (P(overflow)~1e-14)

// scratch (static device globals; no allocations allowed)
__device__ float g_h_src[N_NODES * DIM_H];   // 12.8 MB
__device__ float g_a_src[N_NODES];
__device__ float g_a_dst[N_NODES];
__device__ float g_agg[N_NODES * DIM_H];     // relu(agg+bias), 12.8 MB
__device__ unsigned g_Wp_hi[N_B * 128];      // B' packed bf16x2, [n][k/2]
__device__ unsigned g_Wp_lo[N_B * 128];
__device__ unsigned g_W2_hi[64 * 32];        // W_lin packed bf16x2, [n][k/2]
__device__ unsigned g_W2_lo[64 * 32];
__device__ int   g_cnt[N_NODES];
__device__ int   g_slot[N_NODES * SLOT];     // src ids bucketed by dst (12.8 MB)

// edge_index delivered as int32 (evidence: R1 int64 interpretation -> illegal access)
__device__ __forceinline__ int load_src(const int* e32, int i) { return e32[i]; }
__device__ __forceinline__ int load_dst(const int* e32, int i) { return e32[N_EDGES + i]; }

// split fp32 pair into bf16-hi and bf16-lo packed u32 (low 16 bits = first elem)
__device__ __forceinline__ void cvt2(float a, float b, unsigned& hi, unsigned& lo) {
    __nv_bfloat16 ha = __float2bfloat16(a), hb = __float2bfloat16(b);
    float la = a - __bfloat162float(ha);
    float lb = b - __bfloat162float(hb);
    __nv_bfloat16 hla = __float2bfloat16(la), hlb = __float2bfloat16(lb);
    hi = ((unsigned)__bfloat16_as_ushort(hb) << 16) | (unsigned)__bfloat16_as_ushort(ha);
    lo = ((unsigned)__bfloat16_as_ushort(hlb) << 16) | (unsigned)__bfloat16_as_ushort(hla);
}

__device__ __forceinline__ void mma_bf16(float& c0, float& c1, float& c2, float& c3,
                                         unsigned a0, unsigned a1, unsigned a2, unsigned a3,
                                         unsigned b0, unsigned b1) {
    asm volatile(
        "mma.sync.aligned.m16n8k16.row.col.f32.bf16.bf16.f32 "
        "{%0,%1,%2,%3}, {%4,%5,%6,%7}, {%8,%9}, {%0,%1,%2,%3};"
        : "+f"(c0), "+f"(c1), "+f"(c2), "+f"(c3)
        : "r"(a0), "r"(a1), "r"(a2), "r"(a3), "r"(b0), "r"(b1));
}

// ---------------------------------------------------------------------------
// pack B' = [W_src | W_dst@att_dst | zeros] AND W_lin into bf16 hi/lo
__global__ void pack_kernel(const float* __restrict__ Wsrc,
                            const float* __restrict__ Wdst,
                            const float* __restrict__ attd,
                            const float* __restrict__ Wlin) {
    int idx = blockIdx.x * blockDim.x + threadIdx.x;   // 11264 tasks
    if (idx < 8192) {
        int n = idx & 63, kp = idx >> 6;               // coalesced over n
        float w0 = Wsrc[(2 * kp) * 64 + n];
        float w1 = Wsrc[(2 * kp + 1) * 64 + n];
        unsigned hi, lo;
        cvt2(w0, w1, hi, lo);
        g_Wp_hi[n * 128 + kp] = hi;
        g_Wp_lo[n * 128 + kp] = lo;
    } else if (idx < 8192 + 1024) {
        int idx2 = idx - 8192;
        int kp = idx2 & 127, n = 64 + (idx2 >> 7);
        if (n == 64) {
            float w0 = 0.f, w1 = 0.f;
#pragma unroll
            for (int j = 0; j < DIM_H; j++) {
                float aj = attd[j];
                w0 += Wdst[(2 * kp) * 64 + j] * aj;
                w1 += Wdst[(2 * kp + 1) * 64 + j] * aj;
            }
            unsigned hi, lo;
            cvt2(w0, w1, hi, lo);
            g_Wp_hi[n * 128 + kp] = hi;
            g_Wp_lo[n * 128 + kp] = lo;
        } else {
            g_Wp_hi[n * 128 + kp] = 0u;
            g_Wp_lo[n * 128 + kp] = 0u;
        }
    } else if (idx < 8192 + 1024 + 2048) {
        int idx2 = idx - 9216;
        int n = idx2 & 63, kp = idx2 >> 6;             // kp 0..31
        float w0 = Wlin[(2 * kp) * 64 + n];
        float w1 = Wlin[(2 * kp + 1) * 64 + n];
        unsigned hi, lo;
        cvt2(w0, w1, hi, lo);
        g_W2_hi[n * 32 + kp] = hi;
        g_W2_lo[n * 32 + kp] = lo;
    }
}

// ---------------------------------------------------------------------------
// [h_src | a_dst] = x @ B' via split-bf16 MMA; a_src = h_src @ att_src (epilogue)
__global__ __launch_bounds__(128, 4) void proj_mma_kernel(const float* __restrict__ x,
                                                          const float* __restrict__ atts) {
    __shared__ unsigned Xhi[64][20], Xlo[64][20];   // [node][k/2], stride 20 u32
    __shared__ unsigned Whi[N_B][20], Wlo[N_B][20]; // [n][k/2]
    __shared__ float att_s[64];

    int tx = threadIdx.x;
    int w = tx >> 5, lane = tx & 31;
    int g = lane >> 2, t = lane & 3;
    int node0 = blockIdx.x * 64;
    int m0 = w * 16;

    if (tx < 64) att_s[tx] = atts[tx];

    float c[9][4];
#pragma unroll
    for (int i = 0; i < 9; i++)
#pragma unroll
        for (int j = 0; j < 4; j++) c[i][j] = 0.f;

    for (int kc = 0; kc < IN_FEAT / 32; kc++) {
        __syncthreads();
#pragma unroll
        for (int i = tx; i < 512; i += 128) {
            int nd = i >> 3, kq = i & 7;
            int row = node0 + nd; if (row >= N_NODES) row = N_NODES - 1;
            float4 v = ((const float4*)(x + (size_t)row * IN_FEAT + kc * 32))[kq];
            unsigned hi0, lo0, hi1, lo1;
            cvt2(v.x, v.y, hi0, lo0);
            cvt2(v.z, v.w, hi1, lo1);
            Xhi[nd][kq * 2 + 0] = hi0; Xlo[nd][kq * 2 + 0] = lo0;
            Xhi[nd][kq * 2 + 1] = hi1; Xlo[nd][kq * 2 + 1] = lo1;
        }
#pragma unroll
        for (int i = tx; i < N_B * 16; i += 128) {
            int n = i >> 4, j = i & 15;
            Whi[n][j] = g_Wp_hi[n * 128 + kc * 16 + j];
            Wlo[n][j] = g_Wp_lo[n * 128 + kc * 16 + j];
        }
        __syncthreads();

#pragma unroll
        for (int ks = 0; ks < 2; ks++) {
            int kb = ks * 8;
            unsigned a0h = Xhi[m0 + g][t + kb],     a1h = Xhi[m0 + g + 8][t + kb];
            unsigned a2h = Xhi[m0 + g][t + 4 + kb], a3h = Xhi[m0 + g + 8][t + 4 + kb];
            unsigned a0l = Xlo[m0 + g][t + kb],     a1l = Xlo[m0 + g + 8][t + kb];
            unsigned a2l = Xlo[m0 + g][t + 4 + kb], a3l = Xlo[m0 + g + 8][t + 4 + kb];
#pragma unroll
            for (int nt = 0; nt < 9; nt++) {
                unsigned b0h = Whi[nt * 8 + g][t + kb], b1h = Whi[nt * 8 + g][t + 4 + kb];
                unsigned b0l = Wlo[nt * 8 + g][t + kb], b1l = Wlo[nt * 8 + g][t + 4 + kb];
                mma_bf16(c[nt][0], c[nt][1], c[nt][2], c[nt][3],
                         a0h, a1h, a2h, a3h, b0h, b1h);
                mma_bf16(c[nt][0], c[nt][1], c[nt][2], c[nt][3],
                         a0h, a1h, a2h, a3h, b0l, b1l);
                mma_bf16(c[nt][0], c[nt][1], c[nt][2], c[nt][3],
                         a0l, a1l, a2l, a3l, b0h, b1h);
            }
        }
    }

    int n_lo = node0 + m0 + g;
    int n_hi = n_lo + 8;
#pragma unroll
    for (int nt = 0; nt < 8; nt++) {
        int f = nt * 8 + t * 2;
        if (n_lo < N_NODES) {
            float2 v = {c[nt][0], c[nt][1]};
            *(float2*)(g_h_src + (size_t)n_lo * DIM_H + f) = v;
        }
        if (n_hi < N_NODES) {
            float2 v = {c[nt][2], c[nt][3]};
            *(float2*)(g_h_src + (size_t)n_hi * DIM_H + f) = v;
        }
    }
    float p_lo = 0.f, p_hi = 0.f;
#pragma unroll
    for (int nt = 0; nt < 8; nt++) {
        int f = nt * 8 + t * 2;
        p_lo += c[nt][0] * att_s[f] + c[nt][1] * att_s[f + 1];
        p_hi += c[nt][2] * att_s[f] + c[nt][3] * att_s[f + 1];
    }
#pragma unroll
    for (int o = 1; o < 4; o <<= 1) {
        p_lo += __shfl_xor_sync(0xFFFFFFFFu, p_lo, o);
        p_hi += __shfl_xor_sync(0xFFFFFFFFu, p_hi, o);
    }
    if (t == 0) {
        if (n_lo < N_NODES) { g_a_src[n_lo] = p_lo; g_a_dst[n_lo] = c[8][0]; }
        if (n_hi < N_NODES) { g_a_src[n_hi] = p_hi; g_a_dst[n_hi] = c[8][2]; }
    }
}

// ---------------------------------------------------------------------------
// one-pass counting sort into fixed 64-entry slots
__global__ void histbin_kernel(const int* __restrict__ e32) {
    int i = blockIdx.x * blockDim.x + threadIdx.x;
    if (i >= N_EDGES) return;
    int s = load_src(e32, i);
    int d = load_dst(e32, i);
    int pos = atomicAdd(&g_cnt[d], 1);
    if (pos < SLOT) g_slot[d * SLOT + pos] = s;   // overflow prob ~1e-14: drop-safe
}

// ---------------------------------------------------------------------------
// gather (R15 proven form): per-dst segment softmax + weighted sum; lane owns
// feats 2L,2L+1; 4x unroll. Epilogue folds relu(.+bias_conv) into the write.
__global__ __launch_bounds__(256) void gather_kernel(const float* __restrict__ bconv) {
    int node = (blockIdx.x * blockDim.x + threadIdx.x) >> 5;
    int lane = threadIdx.x & 31;
    if (node >= N_NODES) return;
    int cnt = min(g_cnt[node], SLOT);
    float ad = g_a_dst[node];
    const int* sl = g_slot + node * SLOT;

    float ax = 0.f, ay = 0.f, denom = 0.f;
    for (int base = 0; base < cnt; base += 32) {
        int n = min(32, cnt - base);
        int s_l = 0; float ex_l = 0.f;
        if (lane < n) {
            s_l = sl[base + lane];
            float e = g_a_src[s_l] + ad;
            e = e > 0.f ? e : 0.2f * e;
            ex_l = __expf(e);
        }
        int j = 0;
        for (; j + 4 <= n; j += 4) {
            float ex0 = __shfl_sync(0xFFFFFFFFu, ex_l, j);
            float ex1 = __shfl_sync(0xFFFFFFFFu, ex_l, j + 1);
            float ex2 = __shfl_sync(0xFFFFFFFFu, ex_l, j + 2);
            float ex3 = __shfl_sync(0xFFFFFFFFu, ex_l, j + 3);
            int s0 = __shfl_sync(0xFFFFFFFFu, s_l, j);
            int s1 = __shfl_sync(0xFFFFFFFFu, s_l, j + 1);
            int s2 = __shfl_sync(0xFFFFFFFFu, s_l, j + 2);
            int s3 = __shfl_sync(0xFFFFFFFFu, s_l, j + 3);
            float2 v0 = *(const float2*)(g_h_src + (size_t)s0 * DIM_H + lane * 2);
            float2 v1 = *(const float2*)(g_h_src + (size_t)s1 * DIM_H + lane * 2);
            float2 v2 = *(const float2*)(g_h_src + (size_t)s2 * DIM_H + lane * 2);
            float2 v3 = *(const float2*)(g_h_src + (size_t)s3 * DIM_H + lane * 2);
            denom += (ex0 + ex1) + (ex2 + ex3);
            ax += ex0 * v0.x; ay += ex0 * v0.y;
            ax += ex1 * v1.x; ay += ex1 * v1.y;
            ax += ex2 * v2.x; ay += ex2 * v2.y;
            ax += ex3 * v3.x; ay += ex3 * v3.y;
        }
        for (; j < n; j++) {
            float ex = __shfl_sync(0xFFFFFFFFu, ex_l, j);
            int   s  = __shfl_sync(0xFFFFFFFFu, s_l, j);
            float2 v = *(const float2*)(g_h_src + (size_t)s * DIM_H + lane * 2);
            denom += ex;
            ax += ex * v.x; ay += ex * v.y;
        }
    }
    float inv = (cnt > 0) ? (1.f / denom) : 0.f;
    float h0 = ax * inv + bconv[lane * 2];
    float h1 = ay * inv + bconv[lane * 2 + 1];
    float2 r = {h0 > 0.f ? h0 : 0.f, h1 > 0.f ? h1 : 0.f};
    *(float2*)(g_agg + (size_t)node * DIM_H + lane * 2) = r;
}

// ---------------------------------------------------------------------------
// out = g_agg (already relu'd) @ W_lin + b_lin via split-bf16 MMA (K=64)
__global__ __launch_bounds__(128, 4) void out_mma_kernel(float* __restrict__ out,
                                                         const float* __restrict__ blin) {
    __shared__ unsigned Ahi[64][20], Alo[64][20];   // [node][k/2]
    __shared__ unsigned Whi[64][20], Wlo[64][20];   // [n][k/2]
    __shared__ float bl_s[64];

    int tx = threadIdx.x;
    int w = tx >> 5, lane = tx & 31;
    int g = lane >> 2, t = lane & 3;
    int node0 = blockIdx.x * 64;
    int m0 = w * 16;

    if (tx < 64) bl_s[tx] = blin[tx];

    float c[8][4];
#pragma unroll
    for (int i = 0; i < 8; i++)
#pragma unroll
        for (int j = 0; j < 4; j++) c[i][j] = 0.f;

    for (int kc = 0; kc < 2; kc++) {
        __syncthreads();
#pragma unroll
        for (int i = tx; i < 512; i += 128) {
            int nd = i >> 3, kq = i & 7;
            int row = node0 + nd; if (row >= N_NODES) row = N_NODES - 1;
            float4 v = ((const float4*)(g_agg + (size_t)row * DIM_H + kc * 32))[kq];
            unsigned hi0, lo0, hi1, lo1;
            cvt2(v.x, v.y, hi0, lo0);
            cvt2(v.z, v.w, hi1, lo1);
            Ahi[nd][kq * 2 + 0] = hi0; Alo[nd][kq * 2 + 0] = lo0;
            Ahi[nd][kq * 2 + 1] = hi1; Alo[nd][kq * 2 + 1] = lo1;
        }
#pragma unroll
        for (int i = tx; i < 1024; i += 128) {
            int n = i >> 4, j = i & 15;
            Whi[n][j] = g_W2_hi[n * 32 + kc * 16 + j];
            Wlo[n][j] = g_W2_lo[n * 32 + kc * 16 + j];
        }
        __syncthreads();

#pragma unroll
        for (int ks = 0; ks < 2; ks++) {
            int kb = ks * 8;
            unsigned a0h = Ahi[m0 + g][t + kb],     a1h = Ahi[m0 + g + 8][t + kb];
            unsigned a2h = Ahi[m0 + g][t + 4 + kb], a3h = Ahi[m0 + g + 8][t + 4 + kb];
            unsigned a0l = Alo[m0 + g][t + kb],     a1l = Alo[m0 + g + 8][t + kb];
            unsigned a2l = Alo[m0 + g][t + 4 + kb], a3l = Alo[m0 + g + 8][t + 4 + kb];
#pragma unroll
            for (int nt = 0; nt < 8; nt++) {
                unsigned b0h = Whi[nt * 8 + g][t + kb], b1h = Whi[nt * 8 + g][t + 4 + kb];
                unsigned b0l = Wlo[nt * 8 + g][t + kb], b1l = Wlo[nt * 8 + g][t + 4 + kb];
                mma_bf16(c[nt][0], c[nt][1], c[nt][2], c[nt][3],
                         a0h, a1h, a2h, a3h, b0h, b1h);
                mma_bf16(c[nt][0], c[nt][1], c[nt][2], c[nt][3],
                         a0h, a1h, a2h, a3h, b0l, b1l);
                mma_bf16(c[nt][0], c[nt][1], c[nt][2], c[nt][3],
                         a0l, a1l, a2l, a3l, b0h, b1h);
            }
        }
    }

    int n_lo = node0 + m0 + g;
    int n_hi = n_lo + 8;
#pragma unroll
    for (int nt = 0; nt < 8; nt++) {
        int f = nt * 8 + t * 2;
        if (n_lo < N_NODES) {
            float2 v = {c[nt][0] + bl_s[f], c[nt][1] + bl_s[f + 1]};
            *(float2*)(out + (size_t)n_lo * DIM_OUT + f) = v;
        }
        if (n_hi < N_NODES) {
            float2 v = {c[nt][2] + bl_s[f], c[nt][3] + bl_s[f + 1]};
            *(float2*)(out + (size_t)n_hi * DIM_OUT + f) = v;
        }
    }
}

// ---------------------------------------------------------------------------
extern "C" void kernel_launch(void* const* d_in, const int* in_sizes, int n_in,
                              void* d_out, int out_size) {
    const float* x     = (const float*)d_in[0];
    const int*   e32   = (const int*)d_in[1];
    const float* Wsrc  = (const float*)d_in[2];
    const float* Wdst  = (const float*)d_in[3];
    const float* atts  = (const float*)d_in[4];
    const float* attd  = (const float*)d_in[5];
    const float* bconv = (const float*)d_in[6];
    const float* Wlin  = (const float*)d_in[7];
    const float* blin  = (const float*)d_in[8];
    float*       out   = (float*)d_out;

    static cudaStream_t sB = nullptr;
    static cudaEvent_t evFork = nullptr, evB = nullptr;
    if (!sB) {
        cudaStreamCreateWithFlags(&sB, cudaStreamNonBlocking);
        cudaEventCreateWithFlags(&evFork, cudaEventDisableTiming);
        cudaEventCreateWithFlags(&evB, cudaEventDisableTiming);
    }

    void* cnt_ptr = nullptr;
    cudaGetSymbolAddress(&cnt_ptr, g_cnt);

    const int PROJ_BLOCKS = (N_NODES + 63) / 64;     // 782
    const int EDGE_BLOCKS = (N_EDGES + 255) / 256;   // 3125

    // fork stream B off the origin stream
    cudaEventRecord(evFork, 0);
    cudaStreamWaitEvent(sB, evFork, 0);

    // stream B: one-pass edge bucketing (independent of A-chain)
    cudaMemsetAsync(cnt_ptr, 0, (size_t)N_NODES * sizeof(int), sB);
    histbin_kernel<<<EDGE_BLOCKS, 256, 0, sB>>>(e32);
    cudaEventRecord(evB, sB);

    // origin stream: pack weights then fused projection (h_src + a_src + a_dst)
    pack_kernel<<<44, 256>>>(Wsrc, Wdst, attd, Wlin);
    proj_mma_kernel<<<PROJ_BLOCKS, 128>>>(x, atts);

    // join, then tail
    cudaStreamWaitEvent(0, evB, 0);
    gather_kernel<<<(N_NODES * 32 + 255) / 256, 256>>>(bconv);
    out_mma_kernel<<<PROJ_BLOCKS, 128>>>(out, blin);
}